// round 1
// baseline (speedup 1.0000x reference)
#include <cuda_runtime.h>

#define DF 64   // node feature dim
#define DE 16   // edge feature dim
#define DH 16   // hidden dim of both MLPs
#define DM 64   // message dim
#define DOUT 64 // output dim

#define MAXR (50000 * DM)

// Scratch: per-(node, msg-dim) running max, stored as monotone-encoded uint.
// Key 0 == "no incoming edge" sentinel (only NaN could encode to 0).
__device__ unsigned g_r[MAXR];

__device__ __forceinline__ unsigned enc_key(float f) {
    unsigned u = __float_as_uint(f);
    return (u & 0x80000000u) ? ~u : (u | 0x80000000u);
}

__device__ __forceinline__ float dec_key(unsigned u) {
    if (u == 0u) return 0.0f;  // no in-edges -> reference fills 0
    unsigned b = (u & 0x80000000u) ? (u & 0x7FFFFFFFu) : ~u;
    return __uint_as_float(b);
}

__global__ void init_r(int total) {
    int i = blockIdx.x * blockDim.x + threadIdx.x;
    int stride = gridDim.x * blockDim.x;
    for (; i < total; i += stride) g_r[i] = 0u;
}

// Accumulate one float4 of input against 4 consecutive weight rows (16 wide).
#define ACC4(v, wbase)                                                      \
    {                                                                       \
        const float* _w = (wbase);                                          \
        _Pragma("unroll") for (int _j = 0; _j < DH; _j++)                   \
            h[_j] = fmaf((v).x, _w[_j], h[_j]);                             \
        _Pragma("unroll") for (int _j = 0; _j < DH; _j++)                   \
            h[_j] = fmaf((v).y, _w[DH + _j], h[_j]);                        \
        _Pragma("unroll") for (int _j = 0; _j < DH; _j++)                   \
            h[_j] = fmaf((v).z, _w[2 * DH + _j], h[_j]);                    \
        _Pragma("unroll") for (int _j = 0; _j < DH; _j++)                   \
            h[_j] = fmaf((v).w, _w[3 * DH + _j], h[_j]);                    \
    }

__global__ __launch_bounds__(256) void edge_kernel(
    const float* __restrict__ x, const float* __restrict__ ef,
    const int* __restrict__ src, const int* __restrict__ dst,
    const float* __restrict__ W1, const float* __restrict__ b1,
    const float* __restrict__ W2, const float* __restrict__ b2,
    int E)
{
    __shared__ float sW1[(DE + DF) * DH];  // [80][16] row-major (fan_in, fan_out)
    __shared__ float sW2t[DM * DH];        // transposed: [out j][hidden i]
    __shared__ float sb1[DH];
    __shared__ float sb2[DM];

    for (int i = threadIdx.x; i < (DE + DF) * DH; i += blockDim.x) sW1[i] = W1[i];
    for (int i = threadIdx.x; i < DH * DM; i += blockDim.x) {
        int r = i / DM, c = i % DM;
        sW2t[c * DH + r] = W2[i];
    }
    if (threadIdx.x < DH) sb1[threadIdx.x] = b1[threadIdx.x];
    if (threadIdx.x < DM) sb2[threadIdx.x] = b2[threadIdx.x];
    __syncthreads();

    int e = blockIdx.x * blockDim.x + threadIdx.x;
    if (e >= E) return;

    int s = src[e];
    int d = dst[e];

    float h[DH];
#pragma unroll
    for (int j = 0; j < DH; j++) h[j] = sb1[j];

    // edge_feats part: 16 floats = 4x float4, weight rows 0..15
    const float4* ef4 = reinterpret_cast<const float4*>(ef) + (size_t)e * 4;
#pragma unroll
    for (int k4 = 0; k4 < 4; k4++) {
        float4 v = ef4[k4];
        ACC4(v, &sW1[k4 * 4 * DH]);
    }

    // x[src] part: 64 floats = 16x float4, weight rows 16..79
    const float4* xs = reinterpret_cast<const float4*>(x) + (size_t)s * 16;
#pragma unroll 4
    for (int k4 = 0; k4 < 16; k4++) {
        float4 v = xs[k4];
        ACC4(v, &sW1[(DE + k4 * 4) * DH]);
    }

#pragma unroll
    for (int j = 0; j < DH; j++) h[j] = fmaxf(h[j], 0.0f);

    unsigned rbase = (unsigned)d * DM;
#pragma unroll 8
    for (int j = 0; j < DM; j++) {
        float m = sb2[j];
#pragma unroll
        for (int i = 0; i < DH; i++) m = fmaf(h[i], sW2t[j * DH + i], m);
        atomicMax(&g_r[rbase + j], enc_key(m));  // result unused -> RED.MAX
    }
}

__global__ __launch_bounds__(256) void node_kernel(
    const float* __restrict__ x,
    const float* __restrict__ U1, const float* __restrict__ ub1,
    const float* __restrict__ U2, const float* __restrict__ ub2,
    float* __restrict__ out, int N)
{
    __shared__ float sU1[(DF + DM) * DH];  // [128][16]
    __shared__ float sU2t[DOUT * DH];      // transposed
    __shared__ float sb1[DH];
    __shared__ float sb2[DOUT];

    for (int i = threadIdx.x; i < (DF + DM) * DH; i += blockDim.x) sU1[i] = U1[i];
    for (int i = threadIdx.x; i < DH * DOUT; i += blockDim.x) {
        int r = i / DOUT, c = i % DOUT;
        sU2t[c * DH + r] = U2[i];
    }
    if (threadIdx.x < DH) sb1[threadIdx.x] = ub1[threadIdx.x];
    if (threadIdx.x < DOUT) sb2[threadIdx.x] = ub2[threadIdx.x];
    __syncthreads();

    int n = blockIdx.x * blockDim.x + threadIdx.x;
    if (n >= N) return;

    float h[DH];
#pragma unroll
    for (int j = 0; j < DH; j++) h[j] = sb1[j];

    // x part: weight rows 0..63
    const float4* xs = reinterpret_cast<const float4*>(x) + (size_t)n * 16;
#pragma unroll 4
    for (int k4 = 0; k4 < 16; k4++) {
        float4 v = xs[k4];
        ACC4(v, &sU1[k4 * 4 * DH]);
    }

    // r part: weight rows 64..127
    const uint4* rr = reinterpret_cast<const uint4*>(&g_r[(size_t)n * DM]);
#pragma unroll 4
    for (int k4 = 0; k4 < 16; k4++) {
        uint4 uv = rr[k4];
        float4 v;
        v.x = dec_key(uv.x);
        v.y = dec_key(uv.y);
        v.z = dec_key(uv.z);
        v.w = dec_key(uv.w);
        ACC4(v, &sU1[(DF + k4 * 4) * DH]);
    }

#pragma unroll
    for (int j = 0; j < DH; j++) h[j] = fmaxf(h[j], 0.0f);

    float4* out4 = reinterpret_cast<float4*>(out) + (size_t)n * 16;
#pragma unroll 4
    for (int j4 = 0; j4 < DOUT / 4; j4++) {
        float o[4];
#pragma unroll
        for (int t = 0; t < 4; t++) {
            int j = j4 * 4 + t;
            float m = sb2[j];
#pragma unroll
            for (int i = 0; i < DH; i++) m = fmaf(h[i], sU2t[j * DH + i], m);
            o[t] = m;
        }
        out4[j4] = make_float4(o[0], o[1], o[2], o[3]);
    }
}

extern "C" void kernel_launch(void* const* d_in, const int* in_sizes, int n_in,
                              void* d_out, int out_size)
{
    const float* x   = (const float*)d_in[0];
    const float* ef  = (const float*)d_in[1];
    const int*   src = (const int*)d_in[2];
    const int*   dst = (const int*)d_in[3];
    const float* mW1 = (const float*)d_in[4];
    const float* mb1 = (const float*)d_in[5];
    const float* mW2 = (const float*)d_in[6];
    const float* mb2 = (const float*)d_in[7];
    const float* uW1 = (const float*)d_in[8];
    const float* ub1 = (const float*)d_in[9];
    const float* uW2 = (const float*)d_in[10];
    const float* ub2 = (const float*)d_in[11];

    int N = in_sizes[0] / DF;
    int E = in_sizes[2];
    float* out = (float*)d_out;

    init_r<<<256, 256>>>(N * DM);
    edge_kernel<<<(E + 255) / 256, 256>>>(x, ef, src, dst, mW1, mb1, mW2, mb2, E);
    node_kernel<<<(N + 255) / 256, 256>>>(x, uW1, ub1, uW2, ub2, out, N);
}

// round 2
// speedup vs baseline: 1.2562x; 1.2562x over previous
#include <cuda_runtime.h>

#define NN 50000
#define EE 800000
#define FULLMASK 0xFFFFFFFFu

// CSR scratch (static device globals — no allocations)
__device__ int   g_cnt[NN];
__device__ int   g_off[NN + 1];
__device__ int   g_pos[NN];
__device__ int   g_eid[EE];
__device__ float g_pm [NN * 16];   // x @ msg_W1[16:80]  (per-node msg-MLP1 partial)
__device__ float g_pmU[NN * 16];   // x @ udt_W1[0:64]   (per-node udt-MLP1 partial)

__global__ void zero_cnt(int N) {
    int i = blockIdx.x * blockDim.x + threadIdx.x;
    if (i < N) g_cnt[i] = 0;
}

__global__ void hist_kernel(const int* __restrict__ dst, int E) {
    int i = blockIdx.x * blockDim.x + threadIdx.x;
    if (i < E) atomicAdd(&g_cnt[dst[i]], 1);
}

// Single-block exclusive scan of g_cnt -> g_off, g_pos. 1024 threads, chunked.
__global__ void scan_kernel(int N) {
    __shared__ int part[1024];
    int tid = threadIdx.x;
    int per = (N + 1023) / 1024;
    int start = tid * per;
    int s = 0;
    for (int i = 0; i < per; i++) {
        int idx = start + i;
        if (idx < N) s += g_cnt[idx];
    }
    part[tid] = s;
    __syncthreads();
    for (int d = 1; d < 1024; d <<= 1) {
        int v = (tid >= d) ? part[tid - d] : 0;
        __syncthreads();
        part[tid] += v;
        __syncthreads();
    }
    int run = part[tid] - s;  // exclusive prefix at chunk start
    for (int i = 0; i < per; i++) {
        int idx = start + i;
        if (idx < N) {
            g_off[idx] = run;
            g_pos[idx] = run;
            run += g_cnt[idx];
        }
    }
    if (tid == 1023) g_off[N] = part[1023];
}

__global__ void scatter_kernel(const int* __restrict__ dst, int E) {
    int i = blockIdx.x * blockDim.x + threadIdx.x;
    if (i < E) {
        int slot = atomicAdd(&g_pos[dst[i]], 1);
        g_eid[slot] = i;
    }
}

// Warp per node: pm = x @ W1b (msg rows 16..79), pmU = x @ U1a (udt rows 0..63)
__global__ __launch_bounds__(256) void precompute_kernel(
    const float* __restrict__ x, const float* __restrict__ mW1,
    const float* __restrict__ uW1, int N)
{
    __shared__ float sW[2][64 * 16];
    for (int i = threadIdx.x; i < 64 * 16; i += 256) {
        sW[0][i] = mW1[16 * 16 + i];  // W1b
        sW[1][i] = uW1[i];            // U1a
    }
    __syncthreads();

    int warp = (blockIdx.x * 256 + threadIdx.x) >> 5;
    int lane = threadIdx.x & 31;
    int j = lane & 15, half = lane >> 4;
    if (warp >= N) return;
    const float* w = sW[half];
    float xlo = x[(size_t)warp * 64 + lane];        // cols 0..31 across lanes
    float xhi = x[(size_t)warp * 64 + 32 + lane];   // cols 32..63
    float acc = 0.f;
#pragma unroll 8
    for (int c = 0; c < 32; c++) {
        float a = __shfl_sync(FULLMASK, xlo, c);
        float b = __shfl_sync(FULLMASK, xhi, c);
        acc = fmaf(a, w[c * 16 + j], acc);
        acc = fmaf(b, w[(32 + c) * 16 + j], acc);
    }
    if (half == 0) g_pm [warp * 16 + j] = acc;
    else           g_pmU[warp * 16 + j] = acc;
}

// One warp per destination node: compute messages for all in-edges,
// register max-reduce, then fused update MLP -> out. No global atomics.
__global__ __launch_bounds__(256) void gnn_kernel(
    const float* __restrict__ ef,
    const int* __restrict__ src,
    const float* __restrict__ mW1, const float* __restrict__ mb1,
    const float* __restrict__ mW2, const float* __restrict__ mb2,
    const float* __restrict__ uW1, const float* __restrict__ ub1,
    const float* __restrict__ uW2, const float* __restrict__ ub2,
    float* __restrict__ out, int N)
{
    int warp = (blockIdx.x * 256 + threadIdx.x) >> 5;
    int lane = threadIdx.x & 31;
    int j = lane & 15;
    if (warp >= N) return;
    int v = warp;

    // Per-lane weight registers
    float w1[16], w2a[16], w2b[16];
#pragma unroll
    for (int k = 0; k < 16; k++) w1[k] = mW1[k * 16 + j];            // W1a col j
#pragma unroll
    for (int i = 0; i < 16; i++) {
        w2a[i] = mW2[i * 64 + lane];                                  // W2 col lane
        w2b[i] = mW2[i * 64 + 32 + lane];                             // W2 col lane+32
    }
    float b1j = mb1[j];

    int base = g_off[v];
    int deg  = g_off[v + 1] - base;

    float mx0 = -3.4e38f, mx1 = -3.4e38f;
    int done = 0;
    while (done < deg) {
        int cnt = min(32, deg - done);
        int eid_l = 0, src_l = 0;
        if (lane < cnt) {
            eid_l = g_eid[base + done + lane];
            src_l = src[eid_l];
        }

        // Software-pipelined operand load:
        // lanes 0..15 carry ef[e][j], lanes 16..31 carry pm[src_e][j]
        int e0 = __shfl_sync(FULLMASK, eid_l, 0);
        int s0 = __shfl_sync(FULLMASK, src_l, 0);
        float vcur = (lane >> 4) ? g_pm[s0 * 16 + j] : ef[(size_t)e0 * 16 + j];
        for (int t = 0; t < cnt; t++) {
            float vnext = 0.f;
            if (t + 1 < cnt) {
                int e1 = __shfl_sync(FULLMASK, eid_l, t + 1);
                int s1 = __shfl_sync(FULLMASK, src_l, t + 1);
                vnext = (lane >> 4) ? g_pm[s1 * 16 + j] : ef[(size_t)e1 * 16 + j];
            }
            // h_j = relu(b1_j + pm_j + sum_k ef_k * W1a[k][j])  (lanes j and j+16 redundantly)
            float h = b1j + __shfl_sync(FULLMASK, vcur, 16 + j);
#pragma unroll
            for (int k = 0; k < 16; k++)
                h = fmaf(__shfl_sync(FULLMASK, vcur, k), w1[k], h);
            h = fmaxf(h, 0.f);
            // m_{lane}, m_{lane+32} = sum_i h_i * W2[i][.]
            float m0 = 0.f, m1 = 0.f;
#pragma unroll
            for (int i = 0; i < 16; i++) {
                float hi = __shfl_sync(FULLMASK, h, i);
                m0 = fmaf(hi, w2a[i], m0);
                m1 = fmaf(hi, w2b[i], m1);
            }
            mx0 = fmaxf(mx0, m0);
            mx1 = fmaxf(mx1, m1);
            vcur = vnext;
        }
        done += cnt;
    }

    // r = max(m) + b2 (bias is constant per column, so add after max);
    // nodes with no in-edges get r = 0 (DGL/reference semantics)
    float r0 = (deg > 0) ? mx0 + mb2[lane]      : 0.f;
    float r1 = (deg > 0) ? mx1 + mb2[32 + lane] : 0.f;

    // Update MLP: h2_j = relu(pmU_j + ub1_j + sum_k r_k * U1b[k][j])
    float h2 = g_pmU[v * 16 + j] + ub1[j];
#pragma unroll 8
    for (int k = 0; k < 32; k++) {
        float ra = __shfl_sync(FULLMASK, r0, k);   // r_k
        float rb = __shfl_sync(FULLMASK, r1, k);   // r_{k+32}
        h2 = fmaf(ra, uW1[(64 + k) * 16 + j], h2);
        h2 = fmaf(rb, uW1[(96 + k) * 16 + j], h2);
    }
    h2 = fmaxf(h2, 0.f);

    // out_{lane}, out_{lane+32} = ub2 + sum_i h2_i * U2[i][.]
    float o0 = ub2[lane], o1 = ub2[32 + lane];
#pragma unroll
    for (int i = 0; i < 16; i++) {
        float hi = __shfl_sync(FULLMASK, h2, i);
        o0 = fmaf(hi, uW2[i * 64 + lane], o0);
        o1 = fmaf(hi, uW2[i * 64 + 32 + lane], o1);
    }
    out[(size_t)v * 64 + lane]      = o0;
    out[(size_t)v * 64 + 32 + lane] = o1;
}

extern "C" void kernel_launch(void* const* d_in, const int* in_sizes, int n_in,
                              void* d_out, int out_size)
{
    const float* x   = (const float*)d_in[0];
    const float* ef  = (const float*)d_in[1];
    const int*   src = (const int*)d_in[2];
    const int*   dst = (const int*)d_in[3];
    const float* mW1 = (const float*)d_in[4];
    const float* mb1 = (const float*)d_in[5];
    const float* mW2 = (const float*)d_in[6];
    const float* mb2 = (const float*)d_in[7];
    const float* uW1 = (const float*)d_in[8];
    const float* ub1 = (const float*)d_in[9];
    const float* uW2 = (const float*)d_in[10];
    const float* ub2 = (const float*)d_in[11];

    int N = in_sizes[0] / 64;
    int E = in_sizes[2];
    float* out = (float*)d_out;

    zero_cnt<<<(N + 255) / 256, 256>>>(N);
    hist_kernel<<<(E + 255) / 256, 256>>>(dst, E);
    scan_kernel<<<1, 1024>>>(N);
    scatter_kernel<<<(E + 255) / 256, 256>>>(dst, E);
    precompute_kernel<<<(N * 32 + 255) / 256, 256>>>(x, mW1, uW1, N);
    gnn_kernel<<<(N * 32 + 255) / 256, 256>>>(ef, src,
                                              mW1, mb1, mW2, mb2,
                                              uW1, ub1, uW2, ub2,
                                              out, N);
}